// round 15
// baseline (speedup 1.0000x reference)
#include <cuda_runtime.h>
#include <cuda_fp16.h>

// ---------------- problem constants ----------------
#define NBLK 128        // 64 batch-pairs x 2 CTAs (plain grid, no clusters)
#define NTHR 1024
#define LPn  128
#define Bn   64

// packed-weight tile grids (16k x 8j tiles, B-fragment order)
#define WV_NCH  10
#define WV_NJT  20
#define WHH_NCH 10
#define WHH_NJT 60
#define WGC_NCH 10
#define WGC_NJT 78
#define WIH_NCH 40
#define WIH_NJT 64

// ---------------- device scratch ----------------
__device__ float d_WpE[150 * 152];
__device__ float d_WqE[150 * 152];
__device__ float d_WgU[600 * 152];
__device__ uint2 g_WvPk [WV_NCH  * WV_NJT  * 32];
__device__ uint2 g_WhhPk[WHH_NCH * WHH_NJT * 32];
__device__ uint2 g_WgCPk[WGC_NCH * WGC_NJT * 32];
__device__ uint2 g_WihPk[WIH_NCH * WIH_NJT * 32];
__device__ float d_wup[Bn * LPn * 150];
__device__ float d_gu [Bn * LPn * 600];
// pairwise exchange buffers (tiny, L2-resident; stcg/ldcg only)
__device__ float    d_xbse[Bn][152];
__device__ float    d_xgh [Bn][456];
__device__ float    d_xsr [Bn][128];
__device__ float    d_xcc [Bn][152];
__device__ unsigned d_xcp [Bn][80];
__device__ unsigned d_xrg [Bn][304];
__device__ float    d_xgi [Bn][456];
__device__ float    d_xv  [Bn][152];
__device__ unsigned g_pflag[Bn * 2];   // monotonic pairwise flags
__device__ unsigned g_flags[NBLK];     // prologue grid barrier
__device__ unsigned g_rel2;

// ---------------- smem layout (float slots) ----------------
#define WUQ_S  0                 // Wuq fp32 [l*153+h] own 64 rows; P1: Up staging
#define UQH_S  19584             // Uq fp16 full (9728 slots)
#define SCR    29312
#define V_S    (SCR + 0)         // 152
#define VB_S   (SCR + 152)       // 152
#define U_S    (SCR + 304)       // 152
#define BSE_S  (SCR + 456)       // 152
#define CC_S   (SCR + 608)       // 152
#define SRAW_S (SCR + 760)       // 128
#define A_S    (SCR + 888)       // 128
#define GU_S   (SCR + 1016)      // 600
#define GH_S   (SCR + 1616)      // 456
#define GI_S   (SCR + 2072)      // 456
#define VP_S   (SCR + 2528)      // 80 uint pairs of v
#define CP2_S  (SCR + 2608)      // 80 uint pairs of cc
#define RGP_S  (SCR + 2688)      // 320 uint pairs of rg
#define WVP_S  (SCR + 3008)      // 2 x 160
#define GHP_S  (SCR + 3328)      // 2 x 480
#define BP_S   (SCR + 4288)      // 2 x 624
#define CPP_S  (SCR + 5536)      // 4 x 512
#define CCP_S  (SCR + 7584)      // 8 x 152
#define AP_S   (SCR + 8800)      // 512
#define SMEM_FL (SCR + 9312)     // 38624 floats
#define SMEM_BYTES (SMEM_FL * 4) // 154496 B

// ---------------- helpers ----------------
__device__ __forceinline__ float warp_max_all(float v) {
#pragma unroll
    for (int o = 16; o > 0; o >>= 1) v = fmaxf(v, __shfl_xor_sync(0xffffffffu, v, o));
    return v;
}
__device__ __forceinline__ float warp_sum_all(float v) {
#pragma unroll
    for (int o = 16; o > 0; o >>= 1) v += __shfl_xor_sync(0xffffffffu, v, o);
    return v;
}
__device__ __forceinline__ float fast_sig(float x) {
    return 1.0f / (1.0f + __expf(-x));
}
__device__ __forceinline__ float fast_tanh(float x) {
    float cx = fminf(fmaxf(x, -15.0f), 15.0f);
    float e  = __expf(2.0f * cx);
    return __fdividef(e - 1.0f, e + 1.0f);
}
__device__ __forceinline__ float tanh_fastest(float x) {
    float y;
    asm("tanh.approx.f32 %0, %1;" : "=f"(y) : "f"(x));
    return y;
}
__device__ __forceinline__ unsigned pack2(float x, float y) {
    __half2 h = __floats2half2_rn(x, y);
    return *reinterpret_cast<unsigned*>(&h);
}

// m16n8k16 f16 MMA, f32 accumulate (GEMV: A row 0 only)
__device__ __forceinline__ void mma16816(float* d, unsigned a0, unsigned a1,
                                         unsigned b0, unsigned b1) {
    asm volatile(
        "mma.sync.aligned.m16n8k16.row.col.f32.f16.f16.f32 "
        "{%0,%1,%2,%3}, {%4,%5,%6,%7}, {%8,%9}, {%0,%1,%2,%3};"
        : "+f"(d[0]), "+f"(d[1]), "+f"(d[2]), "+f"(d[3])
        : "r"(a0), "r"(0u), "r"(a1), "r"(0u), "r"(b0), "r"(b1));
}
template<int NT>
__device__ __forceinline__ void gemv_acc(float d[][4], const uint2* __restrict__ Wpk,
                                         int njt, int kc0, int kc1, int jt0,
                                         const unsigned* __restrict__ xp, int ln) {
    for (int kc = kc0; kc < kc1; kc++) {
        unsigned a0 = 0, a1 = 0;
        if (ln < 4) { a0 = xp[kc * 8 + ln]; a1 = xp[kc * 8 + 4 + ln]; }
        const uint2* wr = Wpk + (kc * njt + jt0) * 32 + ln;
#pragma unroll
        for (int t = 0; t < NT; t++) {
            uint2 bb = __ldg(&wr[t * 32]);
            mma16816(d[t], a0, a1, bb.x, bb.y);
        }
    }
}
template<int NT>
__device__ __forceinline__ void store_part(const float d[][4], float* dst,
                                           int jt0, int ln) {
    if (ln < 4) {
#pragma unroll
        for (int t = 0; t < NT; t++)
            *(float2*)(dst + (jt0 + t) * 8 + 2 * ln) = make_float2(d[t][0], d[t][1]);
    }
}

// Pairwise sync: battle-tested release/acquire flag pattern (rounds 6-13).
__device__ __forceinline__ void psync(unsigned& pc, int b, int rank) {
    __syncthreads();
    if (threadIdx.x == 0) {
        unsigned t = ++pc;
        asm volatile("st.release.gpu.u32 [%0], %1;"
                     :: "l"(&g_pflag[2 * b + rank]), "r"(t) : "memory");
        unsigned r;
        do {
            asm volatile("ld.acquire.gpu.u32 %0, [%1];"
                         : "=r"(r) : "l"(&g_pflag[2 * b + (rank ^ 1)]));
        } while (r < t);
    }
    __syncthreads();
}

// Prologue grid barrier (flag array, monotonic, atomic-free).
__device__ __forceinline__ void gsync(unsigned& gen) {
    __syncthreads();
    const unsigned target = gen + 1u;
    if (blockIdx.x == 0) {
        if (threadIdx.x < 32) {
            const int ln = threadIdx.x;
            if (ln == 0) *((volatile unsigned*)&g_flags[0]) = target;
            bool ok;
            do {
                unsigned f0, f1, f2, f3;
                asm volatile("ld.acquire.gpu.u32 %0, [%1];" : "=r"(f0) : "l"(&g_flags[ln]));
                asm volatile("ld.acquire.gpu.u32 %0, [%1];" : "=r"(f1) : "l"(&g_flags[ln + 32]));
                asm volatile("ld.acquire.gpu.u32 %0, [%1];" : "=r"(f2) : "l"(&g_flags[ln + 64]));
                asm volatile("ld.acquire.gpu.u32 %0, [%1];" : "=r"(f3) : "l"(&g_flags[ln + 96]));
                ok = (f0 >= target) & (f1 >= target) & (f2 >= target) & (f3 >= target);
            } while (!__all_sync(0xffffffffu, ok));
            if (ln == 0)
                asm volatile("st.release.gpu.u32 [%0], %1;" :: "l"(&g_rel2), "r"(target) : "memory");
        }
    } else {
        if (threadIdx.x == 0) {
            asm volatile("st.release.gpu.u32 [%0], %1;"
                         :: "l"(&g_flags[blockIdx.x]), "r"(target) : "memory");
            unsigned r;
            do {
                asm volatile("ld.acquire.gpu.u32 %0, [%1];" : "=r"(r) : "l"(&g_rel2));
            } while (r < target);
        }
    }
    gen = target;
    __syncthreads();
}

// ---------------- the persistent kernel: 2 plain CTAs per batch ----------------
__global__ void __launch_bounds__(NTHR, 1) pqm_kernel(
    const float* __restrict__ Up, const float* __restrict__ Uq,
    const float* __restrict__ Wp, const float* __restrict__ Wq,
    const float* __restrict__ Wv, const float* __restrict__ Wg,
    const float* __restrict__ Vmat, const float* __restrict__ v0,
    const float* __restrict__ W_ih, const float* __restrict__ W_hh,
    const float* __restrict__ b_ih, const float* __restrict__ b_hh,
    float* __restrict__ out)
{
    extern __shared__ float sm[];
    __half* UQH = (__half*)(sm + UQH_S);
    unsigned* vpair  = (unsigned*)(sm + VP_S);
    unsigned* ccpair = (unsigned*)(sm + CP2_S);
    unsigned* rgpair = (unsigned*)(sm + RGP_S);
    const int tid = threadIdx.x;
    const int b    = blockIdx.x >> 1;
    const int rank = blockIdx.x & 1;
    const int w   = tid >> 5, ln = tid & 31;
    // value splits
    const int HL  = rank ? 80 : 0,  HN  = rank ? 70 : 80;    // h (wup/bse/GRU/v); = wv jt10
    const int PHL = rank ? 0 : 80,  PHN = rank ? 80 : 70;
    const int GJL = rank ? 232 : 0, GJN = rank ? 218 : 232;  // gh/gi j; = jt29
    const int PGL = rank ? 0 : 232, PGN = rank ? 232 : 218;
    const int DL  = rank ? 76 : 0,  DN  = rank ? 74 : 76;    // cc d
    const int PN  = DN >> 1;                                  // own cc pairs
    const int PDL = rank ? 0 : 76,  PPN = rank ? 38 : 37;    // peer cc pairs

    unsigned gen = *((volatile unsigned*)&g_rel2);
    unsigned pc  = *((volatile unsigned*)&g_pflag[2 * b + rank]);

    // ======== P0: folds + packed fp16 B-fragment weight builds ========
    const int gid = blockIdx.x * NTHR + tid;
    const int gstride = NBLK * NTHR;
    for (int idx = gid; idx < 150 * 152; idx += gstride) {
        int h = idx / 152, d = idx - h * 152;
        d_WpE[idx] = (d < 150) ? Wp[h * 300 + d] + Wp[h * 300 + 150 + d] : 0.f;
        d_WqE[idx] = (d < 150) ? Wq[h * 300 + d] + Wq[h * 300 + 150 + d] : 0.f;
    }
    for (int idx = gid; idx < 600 * 152; idx += gstride) {
        int j = idx / 152, k = idx - j * 152;
        d_WgU[idx] = (k < 150) ? Wg[j * 600 + k] + Wg[j * 600 + 150 + k] : 0.f;
    }
    for (int idx = gid; idx < WV_NCH * WV_NJT * 32; idx += gstride) {
        int lane = idx & 31, rest = idx >> 5;
        int jt = rest % WV_NJT, kc = rest / WV_NJT;
        int m = lane & 3, j = 8 * jt + (lane >> 2);
        int k0 = kc * 16 + 2 * m;
        float v00 = 0.f, v01 = 0.f, v10 = 0.f, v11 = 0.f;
        if (j < 150) {
            if (k0     < 150) v00 = Wv[j * 150 + k0];
            if (k0 + 1 < 150) v01 = Wv[j * 150 + k0 + 1];
            if (k0 + 8 < 150) v10 = Wv[j * 150 + k0 + 8];
            if (k0 + 9 < 150) v11 = Wv[j * 150 + k0 + 9];
        }
        g_WvPk[idx] = make_uint2(pack2(v00, v01), pack2(v10, v11));
    }
    for (int idx = gid; idx < WHH_NCH * WHH_NJT * 32; idx += gstride) {
        int lane = idx & 31, rest = idx >> 5;
        int jt = rest % WHH_NJT, kc = rest / WHH_NJT;
        int m = lane & 3, j = 8 * jt + (lane >> 2);
        int k0 = kc * 16 + 2 * m;
        float v00 = 0.f, v01 = 0.f, v10 = 0.f, v11 = 0.f;
        if (j < 450) {
            if (k0     < 150) v00 = W_hh[j * 150 + k0];
            if (k0 + 1 < 150) v01 = W_hh[j * 150 + k0 + 1];
            if (k0 + 8 < 150) v10 = W_hh[j * 150 + k0 + 8];
            if (k0 + 9 < 150) v11 = W_hh[j * 150 + k0 + 9];
        }
        g_WhhPk[idx] = make_uint2(pack2(v00, v01), pack2(v10, v11));
    }
    for (int idx = gid; idx < WGC_NCH * WGC_NJT * 32; idx += gstride) {
        int lane = idx & 31, rest = idx >> 5;
        int jt = rest % WGC_NJT, kc = rest / WGC_NJT;
        int m = lane & 3, j = 8 * jt + (lane >> 2);
        int k0 = kc * 16 + 2 * m;
        float v00 = 0.f, v01 = 0.f, v10 = 0.f, v11 = 0.f;
        if (j < 600) {
            if (k0     < 150) v00 = Wg[j * 600 + 300 + k0]     + Wg[j * 600 + 450 + k0];
            if (k0 + 1 < 150) v01 = Wg[j * 600 + 300 + k0 + 1] + Wg[j * 600 + 450 + k0 + 1];
            if (k0 + 8 < 150) v10 = Wg[j * 600 + 300 + k0 + 8] + Wg[j * 600 + 450 + k0 + 8];
            if (k0 + 9 < 150) v11 = Wg[j * 600 + 300 + k0 + 9] + Wg[j * 600 + 450 + k0 + 9];
        }
        g_WgCPk[idx] = make_uint2(pack2(v00, v01), pack2(v10, v11));
    }
    for (int idx = gid; idx < WIH_NCH * WIH_NJT * 32; idx += gstride) {
        int lane = idx & 31, rest = idx >> 5;
        int jt = rest % WIH_NJT, kc = rest / WIH_NJT;
        int m = lane & 3, j = 8 * jt + (lane >> 2);
        int k0 = kc * 16 + 2 * m;
        float v00 = 0.f, v01 = 0.f, v10 = 0.f, v11 = 0.f;
        if (j < 450) {
            if (k0     < 600) v00 = W_ih[j * 600 + k0];
            if (k0 + 1 < 600) v01 = W_ih[j * 600 + k0 + 1];
            if (k0 + 8 < 600) v10 = W_ih[j * 600 + k0 + 8];
            if (k0 + 9 < 600) v11 = W_ih[j * 600 + k0 + 9];
        }
        g_WihPk[idx] = make_uint2(pack2(v00, v01), pack2(v10, v11));
    }
    gsync(gen);   // the ONLY grid barrier

    // ======== P1 (per-CTA): own halves of wup/gu/Wuq; full UQH ========
    {
        float* A = sm + WUQ_S;     // Up staging [i*152+k]
        for (int t = tid; t < 128 * 152; t += NTHR) {
            int ii = t / 152, k = t - ii * 152;
            A[t] = (k < 150) ? Up[(ii * Bn + b) * 150 + k] : 0.f;
        }
        __syncthreads();
        for (int task = tid; task < 16 * 300; task += NTHR) {
            int j = 300 * rank + task % 300, it = task / 300;
            float acc[8] = {0.f, 0.f, 0.f, 0.f, 0.f, 0.f, 0.f, 0.f};
            const float4* wr = (const float4*)(d_WgU + j * 152);
            for (int q = 0; q < 38; q++) {
                float4 w4 = wr[q];
#pragma unroll
                for (int ii = 0; ii < 8; ii++) {
                    const float* xr = A + (it * 8 + ii) * 152 + q * 4;
                    acc[ii] += w4.x * xr[0] + w4.y * xr[1] + w4.z * xr[2] + w4.w * xr[3];
                }
            }
#pragma unroll
            for (int ii = 0; ii < 8; ii++)
                d_gu[(b * LPn + it * 8 + ii) * 600 + j] = acc[ii];
        }
        for (int task = tid; task < 16 * HN; task += NTHR) {
            int h = HL + task % HN, it = task / HN;
            float acc[8] = {0.f, 0.f, 0.f, 0.f, 0.f, 0.f, 0.f, 0.f};
            const float4* wr = (const float4*)(d_WpE + h * 152);
            for (int q = 0; q < 38; q++) {
                float4 w4 = wr[q];
#pragma unroll
                for (int ii = 0; ii < 8; ii++) {
                    const float* xr = A + (it * 8 + ii) * 152 + q * 4;
                    acc[ii] += w4.x * xr[0] + w4.y * xr[1] + w4.z * xr[2] + w4.w * xr[3];
                }
            }
#pragma unroll
            for (int ii = 0; ii < 8; ii++)
                d_wup[(b * LPn + it * 8 + ii) * 150 + h] = acc[ii];
        }
        __syncthreads();
        for (int t = tid; t < 128 * 152; t += NTHR) {
            int l = t / 152, d = t - l * 152;
            UQH[t] = __float2half_rn((d < 150) ? Uq[(l * Bn + b) * 150 + d] : 0.f);
        }
        __syncthreads();
        for (int task = tid; task < 8 * 150; task += NTHR) {
            int h = task % 150, lt = 8 * rank + task / 150;
            float acc[8] = {0.f, 0.f, 0.f, 0.f, 0.f, 0.f, 0.f, 0.f};
            const float4* wr = (const float4*)(d_WqE + h * 152);
            for (int q = 0; q < 38; q++) {
                float4 w4 = wr[q];
#pragma unroll
                for (int ii = 0; ii < 8; ii++) {
                    const __half2* xr = (const __half2*)(UQH + (lt * 8 + ii) * 152);
                    float2 xa = __half22float2(xr[2 * q]);
                    float2 xb = __half22float2(xr[2 * q + 1]);
                    acc[ii] += w4.x * xa.x + w4.y * xa.y + w4.z * xb.x + w4.w * xb.y;
                }
            }
#pragma unroll
            for (int ii = 0; ii < 8; ii++)
                sm[WUQ_S + (lt * 8 + ii) * 153 + h] = acc[ii];
        }
        __syncthreads();
        if (tid < 150) {
            sm[V_S + tid]  = v0[b * 150 + tid];
            sm[VB_S + tid] = Vmat[b * 150 + tid];
        }
        __syncthreads();
        if (tid < 80) {
            float x0 = (2 * tid     < 150) ? sm[V_S + 2 * tid]     : 0.f;
            float x1 = (2 * tid + 1 < 150) ? sm[V_S + 2 * tid + 1] : 0.f;
            vpair[tid] = pack2(x0, x1);
        }
        if (tid >= 128 && tid < 133) ccpair[75 + tid - 128] = 0u;
        if (tid >= 160 && tid < 180) rgpair[300 + tid - 160] = 0u;
    }
    __syncthreads();

    // ======== main scan: 128 steps ========
    for (int i = 0; i < LPn; i++) {
        // ---- Stage A: staging(regs) + wv (w0-9) + gh (w10-29) ----
        float stg = 0.f;
        if (tid < 450 + HN) {
            if (tid < 150)           stg = Up[(i * Bn + b) * 150 + tid];
            else if (tid < 150 + HN) stg = d_wup[(b * LPn + i) * 150 + HL + tid - 150];
            else                     stg = d_gu[(b * LPn + i) * 600 + 300 * rank + tid - 150 - HN];
        }
        if (w < 10) {
            int kg = w / 5, jg = w % 5;
            float d[2][4];
#pragma unroll
            for (int t = 0; t < 2; t++) { d[t][0]=d[t][1]=d[t][2]=d[t][3]=0.f; }
            gemv_acc<2>(d, g_WvPk, WV_NJT, kg * 5, kg * 5 + 5, rank * 10 + jg * 2, vpair, ln);
            store_part<2>(d, sm + WVP_S + kg * 160, rank * 10 + jg * 2, ln);
        } else if (w < 30) {
            int wl = w - 10, kg = wl / 10, jg = wl % 10;
            float d[3][4];
#pragma unroll
            for (int t = 0; t < 3; t++) { d[t][0]=d[t][1]=d[t][2]=d[t][3]=0.f; }
            gemv_acc<3>(d, g_WhhPk, WHH_NJT, kg * 5, kg * 5 + 5, 29 * rank + jg * 3, vpair, ln);
            store_part<3>(d, sm + GHP_S + kg * 480, 29 * rank + jg * 3, ln);
        }
        if (tid < 150)           sm[U_S + tid] = stg;
        else if (tid < 150 + HN) sm[BSE_S + HL + tid - 150] = stg;
        else if (tid < 450 + HN) sm[GU_S + 300 * rank + tid - 150 - HN] = stg;
        __syncthreads();
        // ---- combine own bse/gh; post to partner ----
        if (tid < HN) {
            int h = HL + tid;
            float bv = sm[BSE_S + h] + sm[WVP_S + h] + sm[WVP_S + 160 + h];
            sm[BSE_S + h] = bv;
            __stcg(&d_xbse[b][h], bv);
        } else if (tid < HN + GJN) {
            int j = GJL + tid - HN;
            float gv = b_hh[j] + sm[GHP_S + j] + sm[GHP_S + 480 + j];
            sm[GH_S + j] = gv;
            __stcg(&d_xgh[b][j], gv);
        }
        psync(pc, b, rank);   // #1
        if (tid < PHN)                 sm[BSE_S + PHL + tid] = __ldcg(&d_xbse[b][PHL + tid]);
        else if (tid < PHN + PGN)      sm[GH_S + PGL + tid - PHN] = __ldcg(&d_xgh[b][PGL + tid - PHN]);
        __syncthreads();
        // ---- S3: own 64 l x 8 k-groups (R13-identical group bounds) ----
        if (tid < 512) {
            int q = tid & 63, g = tid >> 6;
            int l = 64 * rank + q;
            int k0 = (g * 150) >> 3, k1 = ((g + 1) * 150) >> 3;
            const float* wq = sm + WUQ_S + l * 153;
            float acc = 0.f;
#pragma unroll 10
            for (int k = k0; k < k1; k++)
                acc += tanh_fastest(sm[BSE_S + k] + wq[k]) * sm[VB_S + k];
            sm[AP_S + g * 64 + q] = acc;
        }
        __syncthreads();
        if (tid < 64) {
            float s = 0.f;
#pragma unroll
            for (int g = 0; g < 8; g++) s += sm[AP_S + g * 64 + tid];
            sm[SRAW_S + 64 * rank + tid] = s;
            __stcg(&d_xsr[b][64 * rank + tid], s);
        }
        psync(pc, b, rank);   // #2
        if (tid < 64)
            sm[SRAW_S + 64 * (rank ^ 1) + tid] = __ldcg(&d_xsr[b][64 * (rank ^ 1) + tid]);
        __syncthreads();
        // ---- softmax (warp 0; identical in both CTAs) ----
        if (w == 0) {
            float a0 = sm[SRAW_S + ln],      a1 = sm[SRAW_S + 32 + ln];
            float a2 = sm[SRAW_S + 64 + ln], a3 = sm[SRAW_S + 96 + ln];
            float m = fmaxf(fmaxf(a0, a1), fmaxf(a2, a3));
            m = warp_max_all(m);
            float e0 = __expf(a0 - m), e1 = __expf(a1 - m);
            float e2 = __expf(a2 - m), e3 = __expf(a3 - m);
            float ssum = warp_sum_all(e0 + e1 + e2 + e3);
            float inv = __fdividef(1.0f, ssum);
            sm[A_S + ln] = e0 * inv; sm[A_S + 32 + ln] = e1 * inv;
            sm[A_S + 64 + ln] = e2 * inv; sm[A_S + 96 + ln] = e3 * inv;
        }
        __syncthreads();
        // ---- cc partials: own d-range x 8 l-groups ----
        if (tid < 8 * DN) {
            int lq = tid / DN, d = DL + tid % DN;
            const __half* uq = UQH + lq * 16 * 152 + d;
            const float* av = sm + A_S + lq * 16;
            float acc = 0.f;
#pragma unroll
            for (int q = 0; q < 16; q++) acc += av[q] * __half2float(uq[q * 152]);
            sm[CCP_S + lq * 152 + d] = acc;
        }
        __syncthreads();
        if (tid < PN) {
            int d0 = DL + 2 * tid, d1 = d0 + 1;
            float c0 = 0.f, c1 = 0.f;
#pragma unroll
            for (int g = 0; g < 8; g++) {
                c0 += sm[CCP_S + g * 152 + d0];
                c1 += sm[CCP_S + g * 152 + d1];
            }
            sm[CC_S + d0] = c0; sm[CC_S + d1] = c1;
            unsigned cp = pack2(c0, c1);
            ccpair[(DL >> 1) + tid] = cp;
            __stcg(&d_xcc[b][d0], c0);
            __stcg(&d_xcc[b][d1], c1);
            __stcg(&d_xcp[b][(DL >> 1) + tid], cp);
        }
        psync(pc, b, rank);   // #3
        if (tid < PPN) {
            int d0 = PDL + 2 * tid;
            sm[CC_S + d0]     = __ldcg(&d_xcc[b][d0]);
            sm[CC_S + d0 + 1] = __ldcg(&d_xcc[b][d0 + 1]);
            ccpair[(PDL >> 1) + tid] = __ldcg(&d_xcp[b][(PDL >> 1) + tid]);
        }
        __syncthreads();
        // ---- B mma (w0-25): own jt range ----
        if (w < 26) {
            int kg = w / 13, jg = w % 13;
            int jt0 = (rank ? 37 : 0) + jg * 3;
            float d[3][4];
#pragma unroll
            for (int t = 0; t < 3; t++) { d[t][0]=d[t][1]=d[t][2]=d[t][3]=0.f; }
            gemv_acc<3>(d, g_WgCPk, WGC_NJT, kg * 5, kg * 5 + 5, jt0, ccpair, ln);
            store_part<3>(d, sm + BP_S + kg * 624, jt0, ln);
        }
        __syncthreads();
        // ---- B combine: own 150 j-pairs ----
        if (tid < 150) {
            int jp = 150 * rank + tid;
            float r2[2];
#pragma unroll
            for (int s = 0; s < 2; s++) {
                int j = 2 * jp + s;
                float g = sm[GU_S + j] + sm[BP_S + j] + sm[BP_S + 624 + j];
                float sg = fast_sig(g);
                int km = (j < 150) ? j : (j < 300) ? j - 150 : (j < 450) ? j - 300 : j - 450;
                float rb = (j < 300) ? sm[U_S + km] : sm[CC_S + km];
                r2[s] = sg * rb;
            }
            unsigned rp = pack2(r2[0], r2[1]);
            rgpair[jp] = rp;
            __stcg(&d_xrg[b][jp], rp);
        }
        psync(pc, b, rank);   // #4
        if (tid < 150) {
            int jp = 150 * (rank ^ 1) + tid;
            rgpair[jp] = __ldcg(&d_xrg[b][jp]);
        }
        __syncthreads();
        // ---- C mma (32 warps): own jt range, 4 kg x 8 jg NT4 ----
        {
            int kg = w >> 3, jg = w & 7;
            int jt0 = 29 * rank + jg * 4;
            float d[4][4];
#pragma unroll
            for (int t = 0; t < 4; t++) { d[t][0]=d[t][1]=d[t][2]=d[t][3]=0.f; }
            gemv_acc<4>(d, g_WihPk, WIH_NJT, kg * 10, kg * 10 + 10, jt0, rgpair, ln);
            store_part<4>(d, sm + CPP_S + kg * 512, jt0, ln);
        }
        __syncthreads();
        // ---- gi combine own j ----
        if (tid < GJN) {
            int j = GJL + tid;
            float gv = b_ih[j];
#pragma unroll
            for (int g = 0; g < 4; g++) gv += sm[CPP_S + g * 512 + j];
            sm[GI_S + j] = gv;
            __stcg(&d_xgi[b][j], gv);
        }
        psync(pc, b, rank);   // #5
        if (tid < PGN)
            sm[GI_S + PGL + tid] = __ldcg(&d_xgi[b][PGL + tid]);
        __syncthreads();
        // ---- GRU combine own h ----
        if (tid < HN) {
            int h = HL + tid;
            float r_ = fast_sig(sm[GI_S + h]       + sm[GH_S + h]);
            float z_ = fast_sig(sm[GI_S + 150 + h] + sm[GH_S + 150 + h]);
            float n_ = fast_tanh(sm[GI_S + 300 + h] + r_ * sm[GH_S + 300 + h]);
            float hnew = (1.0f - z_) * n_ + z_ * sm[V_S + h];
            out[(i * Bn + b) * 150 + h] = hnew;
            sm[V_S + h] = hnew;
            __stcg(&d_xv[b][h], hnew);
        }
        psync(pc, b, rank);   // #6
        if (tid < PHN)
            sm[V_S + PHL + tid] = __ldcg(&d_xv[b][PHL + tid]);
        __syncthreads();
        if (tid < 80) {
            float x0 = (2 * tid     < 150) ? sm[V_S + 2 * tid]     : 0.f;
            float x1 = (2 * tid + 1 < 150) ? sm[V_S + 2 * tid + 1] : 0.f;
            vpair[tid] = pack2(x0, x1);
        }
        __syncthreads();
    }
}

// ---------------- launch ----------------
extern "C" void kernel_launch(void* const* d_in, const int* in_sizes, int n_in,
                              void* d_out, int out_size)
{
    const float* Up   = (const float*)d_in[0];
    const float* Uq   = (const float*)d_in[1];
    const float* Wp   = (const float*)d_in[2];
    const float* Wq   = (const float*)d_in[3];
    const float* Wv   = (const float*)d_in[4];
    const float* Wg   = (const float*)d_in[5];
    const float* Vm   = (const float*)d_in[6];
    const float* v0   = (const float*)d_in[7];
    const float* W_ih = (const float*)d_in[8];
    const float* W_hh = (const float*)d_in[9];
    const float* b_ih = (const float*)d_in[10];
    const float* b_hh = (const float*)d_in[11];
    float* out = (float*)d_out;

    cudaFuncSetAttribute(pqm_kernel, cudaFuncAttributeMaxDynamicSharedMemorySize, SMEM_BYTES);
    pqm_kernel<<<NBLK, NTHR, SMEM_BYTES>>>(Up, Uq, Wp, Wq, Wv, Wg, Vm, v0,
                                           W_ih, W_hh, b_ih, b_hh, out);
}

// round 16
// speedup vs baseline: 2.3767x; 2.3767x over previous
#include <cuda_runtime.h>
#include <cuda_fp16.h>

// ---------------- problem constants ----------------
#define NBLK 64
#define NTHR 1024
#define LPn  128
#define Bn   64

// packed-weight tile grids (16k x 8j tiles, B-fragment order)
#define WV_NCH  10
#define WV_NJT  20
#define WHH_NCH 10
#define WHH_NJT 58
#define WGC_NCH 10
#define WGC_NJT 75
#define WIH_NCH 40
#define WIH_NJT 58

// ---------------- device scratch ----------------
__device__ float d_WpE[150 * 152];
__device__ float d_WqE[150 * 152];
__device__ float d_WgU[600 * 152];
__device__ uint2 g_WvPk [WV_NCH  * WV_NJT  * 32];   // Wv^T    (k x j=150)
__device__ uint2 g_WhhPk[WHH_NCH * WHH_NJT * 32];   // W_hh^T  (k x j=450)
__device__ uint2 g_WgCPk[WGC_NCH * WGC_NJT * 32];   // WgC^T   (k x j=600)
__device__ uint2 g_WihPk[WIH_NCH * WIH_NJT * 32];   // W_ih^T  (k=600 x j=450)
__device__ float d_wup[Bn * LPn * 150];
__device__ float d_gu [Bn * LPn * 600];
__device__ unsigned g_flags[NBLK];
__device__ unsigned g_rel2;

// ---------------- smem layout (floats) ----------------
#define WUQ_S  0                      // Wuq fp32 [l*153+h]; P1: Up staging
#define UQH_S  19584                  // Uq fp16 [l*152+d] = 9728 float slots
#define SCR    29312
#define V_S    (SCR + 0)              // 152 fp32 v
#define VB_S   (SCR + 152)            // 152 V row
#define U_S    (SCR + 304)            // 152 u
#define BSE_S  (SCR + 456)            // 152
#define CC_S   (SCR + 608)            // 152 fp32 cc
#define A_S    (SCR + 760)            // 128
#define GU_S   (SCR + 888)            // 600
#define GH_S   (SCR + 1488)           // 464
#define VP_S   (SCR + 1952)           // 80  half2 pairs of v (k pad 160)
#define CP2_S  (SCR + 2032)           // 80  half2 pairs of cc
#define RGP_S  (SCR + 2112)           // 320 half2 pairs of rg (k pad 640)
#define WVP_S  (SCR + 2432)           // 2 x 160 wv partials
#define BP_S   (SCR + 2752)           // 2 x 600 B partials
#define CPP_S  (SCR + 3952)           // 2 x 464 C partials
#define CCP_S  (SCR + 4880)           // 8 x 152 cc partials
#define AP_S   (SCR + 6096)           // 1024 s partials; P1 staging 9728 from here
#define SMEM_FL (SCR + 6096 + 9728)   // 45136 floats
#define SMEM_BYTES (SMEM_FL * 4)      // 180544 B

// ---------------- helpers ----------------
__device__ __forceinline__ float warp_max_all(float v) {
#pragma unroll
    for (int o = 16; o > 0; o >>= 1) v = fmaxf(v, __shfl_xor_sync(0xffffffffu, v, o));
    return v;
}
__device__ __forceinline__ float warp_sum_all(float v) {
#pragma unroll
    for (int o = 16; o > 0; o >>= 1) v += __shfl_xor_sync(0xffffffffu, v, o);
    return v;
}
__device__ __forceinline__ float fast_sig(float x) {
    return 1.0f / (1.0f + __expf(-x));
}
__device__ __forceinline__ float fast_tanh(float x) {
    float cx = fminf(fmaxf(x, -15.0f), 15.0f);
    float e  = __expf(2.0f * cx);
    return __fdividef(e - 1.0f, e + 1.0f);
}
__device__ __forceinline__ float tanh_fastest(float x) {
    float y;
    asm("tanh.approx.f32 %0, %1;" : "=f"(y) : "f"(x));
    return y;
}
__device__ __forceinline__ unsigned pack2(float x, float y) {
    __half2 h = __floats2half2_rn(x, y);
    return *reinterpret_cast<unsigned*>(&h);
}

// m16n8k16 f16 MMA, f32 accumulate. A rows 1-15 zero (GEMV): a-regs {xlow, 0, xhigh, 0}.
__device__ __forceinline__ void mma16816(float* d, unsigned a0, unsigned a1,
                                         unsigned b0, unsigned b1) {
    asm volatile(
        "mma.sync.aligned.m16n8k16.row.col.f32.f16.f16.f32 "
        "{%0,%1,%2,%3}, {%4,%5,%6,%7}, {%8,%9}, {%0,%1,%2,%3};"
        : "+f"(d[0]), "+f"(d[1]), "+f"(d[2]), "+f"(d[3])
        : "r"(a0), "r"(0u), "r"(a1), "r"(0u), "r"(b0), "r"(b1));
}

// GEMV tile loop, FULLY UNROLLED (KC chunks compile-time): all per-chunk LDG
// addresses are independent, so ptxas front-batches them (MLP_eff 12-16)
// instead of one serial L2 latency per chunk.
template<int NT, int KC>
__device__ __forceinline__ void gemv_acc(float d[][4], const uint2* __restrict__ Wpk,
                                         int njt, int kc0, int jt0,
                                         const unsigned* __restrict__ xp, int ln) {
#pragma unroll
    for (int c = 0; c < KC; c++) {
        const int kc = kc0 + c;
        unsigned a0 = 0, a1 = 0;
        if (ln < 4) { a0 = xp[kc * 8 + ln]; a1 = xp[kc * 8 + 4 + ln]; }
        const uint2* wr = Wpk + (kc * njt + jt0) * 32 + ln;
#pragma unroll
        for (int t = 0; t < NT; t++) {
            uint2 bb = __ldg(&wr[t * 32]);
            mma16816(d[t], a0, a1, bb.x, bb.y);
        }
    }
}
template<int NT>
__device__ __forceinline__ void store_part(const float d[][4], float* dst,
                                           int jt0, int ln) {
    if (ln < 4) {
#pragma unroll
        for (int t = 0; t < NT; t++)
            *(float2*)(dst + (jt0 + t) * 8 + 2 * ln) = make_float2(d[t][0], d[t][1]);
    }
}

// Flag-array grid barrier (prologue only). Monotonic, atomic-free.
__device__ __forceinline__ void gsync(unsigned& gen) {
    __syncthreads();
    const unsigned target = gen + 1u;
    if (blockIdx.x == 0) {
        if (threadIdx.x < 32) {
            const int ln = threadIdx.x;
            if (ln == 0) *((volatile unsigned*)&g_flags[0]) = target;
            bool ok;
            do {
                unsigned f0, f1;
                asm volatile("ld.acquire.gpu.u32 %0, [%1];" : "=r"(f0) : "l"(&g_flags[ln]));
                asm volatile("ld.acquire.gpu.u32 %0, [%1];" : "=r"(f1) : "l"(&g_flags[ln + 32]));
                ok = (f0 >= target) & (f1 >= target);
            } while (!__all_sync(0xffffffffu, ok));
            if (ln == 0)
                asm volatile("st.release.gpu.u32 [%0], %1;" :: "l"(&g_rel2), "r"(target) : "memory");
        }
    } else {
        if (threadIdx.x == 0) {
            asm volatile("st.release.gpu.u32 [%0], %1;"
                         :: "l"(&g_flags[blockIdx.x]), "r"(target) : "memory");
            unsigned r;
            do {
                asm volatile("ld.acquire.gpu.u32 %0, [%1];" : "=r"(r) : "l"(&g_rel2));
            } while (r < target);
        }
    }
    gen = target;
    __syncthreads();
}

// ---------------- the persistent kernel: one block per batch ----------------
__global__ void __launch_bounds__(NTHR, 1) pqm_kernel(
    const float* __restrict__ Up, const float* __restrict__ Uq,
    const float* __restrict__ Wp, const float* __restrict__ Wq,
    const float* __restrict__ Wv, const float* __restrict__ Wg,
    const float* __restrict__ Vmat, const float* __restrict__ v0,
    const float* __restrict__ W_ih, const float* __restrict__ W_hh,
    const float* __restrict__ b_ih, const float* __restrict__ b_hh,
    float* __restrict__ out)
{
    extern __shared__ float sm[];
    __half* UQH = (__half*)(sm + UQH_S);
    unsigned* vpair  = (unsigned*)(sm + VP_S);
    unsigned* ccpair = (unsigned*)(sm + CP2_S);
    unsigned* rgpair = (unsigned*)(sm + RGP_S);
    const int tid = threadIdx.x;
    const int b   = blockIdx.x;
    const int w   = tid >> 5, ln = tid & 31;

    unsigned gen = *((volatile unsigned*)&g_rel2);

    // ======== P0: folds + packed fp16 B-fragment weight builds ========
    const int gid = b * NTHR + tid;
    const int gstride = NBLK * NTHR;
    for (int idx = gid; idx < 150 * 152; idx += gstride) {
        int h = idx / 152, d = idx - h * 152;
        d_WpE[idx] = (d < 150) ? Wp[h * 300 + d] + Wp[h * 300 + 150 + d] : 0.f;
        d_WqE[idx] = (d < 150) ? Wq[h * 300 + d] + Wq[h * 300 + 150 + d] : 0.f;
    }
    for (int idx = gid; idx < 600 * 152; idx += gstride) {
        int j = idx / 152, k = idx - j * 152;
        d_WgU[idx] = (k < 150) ? Wg[j * 600 + k] + Wg[j * 600 + 150 + k] : 0.f;
    }
    for (int idx = gid; idx < WV_NCH * WV_NJT * 32; idx += gstride) {
        int lane = idx & 31, rest = idx >> 5;
        int jt = rest % WV_NJT, kc = rest / WV_NJT;
        int m = lane & 3, j = 8 * jt + (lane >> 2);
        int k0 = kc * 16 + 2 * m;
        float v00 = 0.f, v01 = 0.f, v10 = 0.f, v11 = 0.f;
        if (j < 150) {
            if (k0     < 150) v00 = Wv[j * 150 + k0];
            if (k0 + 1 < 150) v01 = Wv[j * 150 + k0 + 1];
            if (k0 + 8 < 150) v10 = Wv[j * 150 + k0 + 8];
            if (k0 + 9 < 150) v11 = Wv[j * 150 + k0 + 9];
        }
        g_WvPk[idx] = make_uint2(pack2(v00, v01), pack2(v10, v11));
    }
    for (int idx = gid; idx < WHH_NCH * WHH_NJT * 32; idx += gstride) {
        int lane = idx & 31, rest = idx >> 5;
        int jt = rest % WHH_NJT, kc = rest / WHH_NJT;
        int m = lane & 3, j = 8 * jt + (lane >> 2);
        int k0 = kc * 16 + 2 * m;
        float v00 = 0.f, v01 = 0.f, v10 = 0.f, v11 = 0.f;
        if (j < 450) {
            if (k0     < 150) v00 = W_hh[j * 150 + k0];
            if (k0 + 1 < 150) v01 = W_hh[j * 150 + k0 + 1];
            if (k0 + 8 < 150) v10 = W_hh[j * 150 + k0 + 8];
            if (k0 + 9 < 150) v11 = W_hh[j * 150 + k0 + 9];
        }
        g_WhhPk[idx] = make_uint2(pack2(v00, v01), pack2(v10, v11));
    }
    for (int idx = gid; idx < WGC_NCH * WGC_NJT * 32; idx += gstride) {
        int lane = idx & 31, rest = idx >> 5;
        int jt = rest % WGC_NJT, kc = rest / WGC_NJT;
        int m = lane & 3, j = 8 * jt + (lane >> 2);
        int k0 = kc * 16 + 2 * m;
        float v00 = 0.f, v01 = 0.f, v10 = 0.f, v11 = 0.f;
        if (k0     < 150) v00 = Wg[j * 600 + 300 + k0]     + Wg[j * 600 + 450 + k0];
        if (k0 + 1 < 150) v01 = Wg[j * 600 + 300 + k0 + 1] + Wg[j * 600 + 450 + k0 + 1];
        if (k0 + 8 < 150) v10 = Wg[j * 600 + 300 + k0 + 8] + Wg[j * 600 + 450 + k0 + 8];
        if (k0 + 9 < 150) v11 = Wg[j * 600 + 300 + k0 + 9] + Wg[j * 600 + 450 + k0 + 9];
        g_WgCPk[idx] = make_uint2(pack2(v00, v01), pack2(v10, v11));
    }
    for (int idx = gid; idx < WIH_NCH * WIH_NJT * 32; idx += gstride) {
        int lane = idx & 31, rest = idx >> 5;
        int jt = rest % WIH_NJT, kc = rest / WIH_NJT;
        int m = lane & 3, j = 8 * jt + (lane >> 2);
        int k0 = kc * 16 + 2 * m;
        float v00 = 0.f, v01 = 0.f, v10 = 0.f, v11 = 0.f;
        if (j < 450) {
            if (k0     < 600) v00 = W_ih[j * 600 + k0];
            if (k0 + 1 < 600) v01 = W_ih[j * 600 + k0 + 1];
            if (k0 + 8 < 600) v10 = W_ih[j * 600 + k0 + 8];
            if (k0 + 9 < 600) v11 = W_ih[j * 600 + k0 + 9];
        }
        g_WihPk[idx] = make_uint2(pack2(v00, v01), pack2(v10, v11));
    }
    gsync(gen);   // the ONLY grid barrier

    // ======== P1 (block-local): per-batch precompute ========
    {
        float* A = sm + WUQ_S;     // Up staging [i*152+k]
        for (int t = tid; t < 128 * 150; t += NTHR) {
            int ii = t / 150, k = t - ii * 150;
            A[ii * 152 + k] = Up[(ii * Bn + b) * 150 + k];
        }
        __syncthreads();
        for (int task = tid; task < 16 * 600; task += NTHR) {
            int j = task % 600, it = task / 600;
            float acc[8] = {0.f, 0.f, 0.f, 0.f, 0.f, 0.f, 0.f, 0.f};
            const float4* wr = (const float4*)(d_WgU + j * 152);
            for (int q = 0; q < 38; q++) {
                float4 w4 = wr[q];
#pragma unroll
                for (int ii = 0; ii < 8; ii++) {
                    const float* xr = A + (it * 8 + ii) * 152 + q * 4;
                    acc[ii] += w4.x * xr[0] + w4.y * xr[1] + w4.z * xr[2] + w4.w * xr[3];
                }
            }
#pragma unroll
            for (int ii = 0; ii < 8; ii++)
                d_gu[(b * LPn + it * 8 + ii) * 600 + j] = acc[ii];
        }
        for (int task = tid; task < 16 * 150; task += NTHR) {
            int h = task % 150, it = task / 150;
            float acc[8] = {0.f, 0.f, 0.f, 0.f, 0.f, 0.f, 0.f, 0.f};
            const float4* wr = (const float4*)(d_WpE + h * 152);
            for (int q = 0; q < 38; q++) {
                float4 w4 = wr[q];
#pragma unroll
                for (int ii = 0; ii < 8; ii++) {
                    const float* xr = A + (it * 8 + ii) * 152 + q * 4;
                    acc[ii] += w4.x * xr[0] + w4.y * xr[1] + w4.z * xr[2] + w4.w * xr[3];
                }
            }
#pragma unroll
            for (int ii = 0; ii < 8; ii++)
                d_wup[(b * LPn + it * 8 + ii) * 150 + h] = acc[ii];
        }
        __syncthreads();
        float* S2 = sm + AP_S;
        for (int ph = 0; ph < 2; ph++) {
            for (int t = tid; t < 64 * 150; t += NTHR) {
                int ll = t / 150, d = t - ll * 150;
                float vv = Uq[((ph * 64 + ll) * Bn + b) * 150 + d];
                S2[ll * 152 + d] = vv;
                UQH[(ph * 64 + ll) * 152 + d] = __float2half_rn(vv);
            }
            __syncthreads();
            for (int task = tid; task < 8 * 150; task += NTHR) {
                int h = task % 150, lt = task / 150;
                float acc[8] = {0.f, 0.f, 0.f, 0.f, 0.f, 0.f, 0.f, 0.f};
                const float4* wr = (const float4*)(d_WqE + h * 152);
                for (int q = 0; q < 38; q++) {
                    float4 w4 = wr[q];
#pragma unroll
                    for (int ii = 0; ii < 8; ii++) {
                        const float* xr = S2 + (lt * 8 + ii) * 152 + q * 4;
                        acc[ii] += w4.x * xr[0] + w4.y * xr[1] + w4.z * xr[2] + w4.w * xr[3];
                    }
                }
#pragma unroll
                for (int ii = 0; ii < 8; ii++)
                    sm[WUQ_S + (ph * 64 + lt * 8 + ii) * 153 + h] = acc[ii];
            }
            __syncthreads();
        }
        if (tid < 150) {
            sm[V_S + tid]  = v0[b * 150 + tid];
            sm[VB_S + tid] = Vmat[b * 150 + tid];
        }
        __syncthreads();
        if (tid < 80) {
            float x0 = (2 * tid     < 150) ? sm[V_S + 2 * tid]     : 0.f;
            float x1 = (2 * tid + 1 < 150) ? sm[V_S + 2 * tid + 1] : 0.f;
            vpair[tid] = pack2(x0, x1);
        }
        if (tid >= 128 && tid < 133) ccpair[75 + tid - 128] = 0u;
        if (tid >= 160 && tid < 180) rgpair[300 + tid - 160] = 0u;
    }
    __syncthreads();

    // ======== main scan: 128 steps, block-local ========
    for (int i = 0; i < LPn; i++) {
        // ---- Stage A: wv mma (w0-7) | gh mma (w8-23) | staging (w24-31) ----
        if (w < 8) {
            int kg = w >> 2, jgl = w & 3;
            float d[5][4];
#pragma unroll
            for (int t = 0; t < 5; t++) { d[t][0]=d[t][1]=d[t][2]=d[t][3]=0.f; }
            gemv_acc<5, 5>(d, g_WvPk, WV_NJT, kg * 5, jgl * 5, vpair, ln);
            store_part<5>(d, sm + WVP_S + kg * 160, jgl * 5, ln);
        } else if (w < 24) {
            int wl = w - 8;
            int jt0, nt4 = (wl < 10);
            jt0 = nt4 ? wl * 4 : 40 + (wl - 10) * 3;
            if (nt4) {
                float d[4][4];
#pragma unroll
                for (int t = 0; t < 4; t++) { d[t][0]=d[t][1]=d[t][2]=d[t][3]=0.f; }
                gemv_acc<4, 10>(d, g_WhhPk, WHH_NJT, 0, jt0, vpair, ln);
                if (ln < 4) {
#pragma unroll
                    for (int t = 0; t < 4; t++) {
                        int j = (jt0 + t) * 8 + 2 * ln;
                        if (j < 450) {
                            sm[GH_S + j]     = d[t][0] + b_hh[j];
                            sm[GH_S + j + 1] = d[t][1] + b_hh[j + 1];
                        }
                    }
                }
            } else {
                float d[3][4];
#pragma unroll
                for (int t = 0; t < 3; t++) { d[t][0]=d[t][1]=d[t][2]=d[t][3]=0.f; }
                gemv_acc<3, 10>(d, g_WhhPk, WHH_NJT, 0, jt0, vpair, ln);
                if (ln < 4) {
#pragma unroll
                    for (int t = 0; t < 3; t++) {
                        int j = (jt0 + t) * 8 + 2 * ln;
                        if (j < 450) {
                            sm[GH_S + j]     = d[t][0] + b_hh[j];
                            sm[GH_S + j + 1] = d[t][1] + b_hh[j + 1];
                        }
                    }
                }
            }
        } else {
            for (int t = tid - 768; t < 900; t += 256) {
                if (t < 150)      sm[U_S + t]         = Up[(i * Bn + b) * 150 + t];
                else if (t < 300) sm[BSE_S + t - 150] = d_wup[(b * LPn + i) * 150 + t - 150];
                else              sm[GU_S + t - 300]  = d_gu[(b * LPn + i) * 600 + t - 300];
            }
        }
        __syncthreads();
        // ---- bse combine ----
        if (tid < 150) sm[BSE_S + tid] += sm[WVP_S + tid] + sm[WVP_S + 160 + tid];
        __syncthreads();
        // ---- S3: s[l] partials (128 l x 8 k-groups) ----
        {
            int l = tid & 127, g = tid >> 7;
            int k0 = (g * 150) >> 3, k1 = ((g + 1) * 150) >> 3;
            const float* wq = sm + WUQ_S + l * 153;
            float acc = 0.f;
#pragma unroll 10
            for (int k = k0; k < k1; k++)
                acc += tanh_fastest(sm[BSE_S + k] + wq[k]) * sm[VB_S + k];
            sm[AP_S + g * 128 + l] = acc;
        }
        __syncthreads();
        // ---- softmax (warp 0) ----
        if (w == 0) {
            float a0 = 0.f, a1 = 0.f, a2 = 0.f, a3 = 0.f;
#pragma unroll
            for (int g = 0; g < 8; g++) {
                const float* apg = sm + AP_S + g * 128;
                a0 += apg[ln]; a1 += apg[32 + ln]; a2 += apg[64 + ln]; a3 += apg[96 + ln];
            }
            float m = fmaxf(fmaxf(a0, a1), fmaxf(a2, a3));
            m = warp_max_all(m);
            float e0 = __expf(a0 - m), e1 = __expf(a1 - m);
            float e2 = __expf(a2 - m), e3 = __expf(a3 - m);
            float ssum = warp_sum_all(e0 + e1 + e2 + e3);
            float inv = __fdividef(1.0f, ssum);
            sm[A_S + ln] = e0 * inv; sm[A_S + 32 + ln] = e1 * inv;
            sm[A_S + 64 + ln] = e2 * inv; sm[A_S + 96 + ln] = e3 * inv;
        }
        __syncthreads();
        // ---- cc partials (8 l-groups x 150 d) ----
        for (int t = tid; t < 1200; t += NTHR) {
            int lq = t / 150, d = t - lq * 150;
            const __half* uq = UQH + lq * 16 * 152 + d;
            const float* av = sm + A_S + lq * 16;
            float acc = 0.f;
#pragma unroll
            for (int q = 0; q < 16; q++) acc += av[q] * __half2float(uq[q * 152]);
            sm[CCP_S + lq * 152 + d] = acc;
        }
        __syncthreads();
        // ---- cc combine (75 thr, 2 cols each) + pairs ----
        if (tid < 75) {
            float c0 = 0.f, c1 = 0.f;
            int d0 = 2 * tid, d1 = d0 + 1;
#pragma unroll
            for (int g = 0; g < 8; g++) {
                c0 += sm[CCP_S + g * 152 + d0];
                c1 += sm[CCP_S + g * 152 + d1];
            }
            sm[CC_S + d0] = c0; sm[CC_S + d1] = c1;
            ccpair[tid] = pack2(c0, c1);
        }
        __syncthreads();
        // ---- B mma (w0-29): bp = cc @ WgC^T partials ----
        if (w < 30) {
            int kg = w / 15, jgl = w - kg * 15;
            float d[5][4];
#pragma unroll
            for (int t = 0; t < 5; t++) { d[t][0]=d[t][1]=d[t][2]=d[t][3]=0.f; }
            gemv_acc<5, 5>(d, g_WgCPk, WGC_NJT, kg * 5, jgl * 5, ccpair, ln);
            store_part<5>(d, sm + BP_S + kg * 600, jgl * 5, ln);
        }
        __syncthreads();
        // ---- B combine (300 thr, 2 j each): rg pairs ----
        if (tid < 300) {
            float r2[2];
#pragma unroll
            for (int s = 0; s < 2; s++) {
                int j = 2 * tid + s;
                float g = sm[GU_S + j] + sm[BP_S + j] + sm[BP_S + 600 + j];
                float sg = fast_sig(g);
                int km = (j < 150) ? j : (j < 300) ? j - 150 : (j < 450) ? j - 300 : j - 450;
                float rb = (j < 300) ? sm[U_S + km] : sm[CC_S + km];
                r2[s] = sg * rb;
            }
            rgpair[tid] = pack2(r2[0], r2[1]);
        }
        __syncthreads();
        // ---- C mma (all 32): cp = rg @ W_ih^T partials ----
        {
            int kg = w >> 4, jgl = w & 15;
            int nt4 = (jgl < 10);
            int jt0 = nt4 ? jgl * 4 : 40 + (jgl - 10) * 3;
            if (nt4) {
                float d[4][4];
#pragma unroll
                for (int t = 0; t < 4; t++) { d[t][0]=d[t][1]=d[t][2]=d[t][3]=0.f; }
                gemv_acc<4, 20>(d, g_WihPk, WIH_NJT, kg * 20, jt0, rgpair, ln);
                store_part<4>(d, sm + CPP_S + kg * 464, jt0, ln);
            } else {
                float d[3][4];
#pragma unroll
                for (int t = 0; t < 3; t++) { d[t][0]=d[t][1]=d[t][2]=d[t][3]=0.f; }
                gemv_acc<3, 20>(d, g_WihPk, WIH_NJT, kg * 20, jt0, rgpair, ln);
                store_part<3>(d, sm + CPP_S + kg * 464, jt0, ln);
            }
        }
        __syncthreads();
        // ---- GRU combine (75 thr, 2 h each) + v pairs ----
        if (tid < 75) {
            float hn2[2];
#pragma unroll
            for (int s = 0; s < 2; s++) {
                int h = 2 * tid + s;
                float ir  = b_ih[h]       + sm[CPP_S + h]       + sm[CPP_S + 464 + h];
                float iz  = b_ih[150 + h] + sm[CPP_S + 150 + h] + sm[CPP_S + 614 + h];
                float in_ = b_ih[300 + h] + sm[CPP_S + 300 + h] + sm[CPP_S + 764 + h];
                float r_ = fast_sig(ir + sm[GH_S + h]);
                float z_ = fast_sig(iz + sm[GH_S + 150 + h]);
                float n_ = fast_tanh(in_ + r_ * sm[GH_S + 300 + h]);
                float hnew = (1.0f - z_) * n_ + z_ * sm[V_S + h];
                out[(i * Bn + b) * 150 + h] = hnew;
                sm[V_S + h] = hnew;
                hn2[s] = hnew;
            }
            vpair[tid] = pack2(hn2[0], hn2[1]);
        }
        __syncthreads();
    }
}

// ---------------- launch ----------------
extern "C" void kernel_launch(void* const* d_in, const int* in_sizes, int n_in,
                              void* d_out, int out_size)
{
    const float* Up   = (const float*)d_in[0];
    const float* Uq   = (const float*)d_in[1];
    const float* Wp   = (const float*)d_in[2];
    const float* Wq   = (const float*)d_in[3];
    const float* Wv   = (const float*)d_in[4];
    const float* Wg   = (const float*)d_in[5];
    const float* Vm   = (const float*)d_in[6];
    const float* v0   = (const float*)d_in[7];
    const float* W_ih = (const float*)d_in[8];
    const float* W_hh = (const float*)d_in[9];
    const float* b_ih = (const float*)d_in[10];
    const float* b_hh = (const float*)d_in[11];
    float* out = (float*)d_out;

    cudaFuncSetAttribute(pqm_kernel, cudaFuncAttributeMaxDynamicSharedMemorySize, SMEM_BYTES);
    pqm_kernel<<<NBLK, NTHR, SMEM_BYTES>>>(Up, Uq, Wp, Wq, Wv, Wg, Vm, v0,
                                           W_ih, W_hh, b_ih, b_hh, out);
}

// round 17
// speedup vs baseline: 2.5604x; 1.0773x over previous
#include <cuda_runtime.h>
#include <cuda_fp16.h>

// ---------------- problem constants ----------------
#define NBLK 64
#define NTHR 1024
#define LPn  128
#define Bn   64

// packed-weight tile grids: 16k x 8j tiles, stored as uint4 per lane per
// TILE-PAIR (two adjacent 8-j tiles per 16B load -> LDG.128, half the LDGs)
#define WV_NCH   10
#define WV_NJT   24    // 12 pairs
#define WHH_NCH  10
#define WHH_NJT  64    // 32 pairs
#define WGC_NCH  10
#define WGC_NJT  80    // 40 pairs
#define WIH_NCH  40
#define WIH_NJT  64    // 32 pairs

// ---------------- device scratch ----------------
__device__ float d_WpE[150 * 152];
__device__ float d_WqE[150 * 152];
__device__ float d_WgU[600 * 152];
__device__ uint4 g_WvPk [WV_NCH  * (WV_NJT  / 2) * 32];  // Wv^T
__device__ uint4 g_WhhPk[WHH_NCH * (WHH_NJT / 2) * 32];  // W_hh^T
__device__ uint4 g_WgCPk[WGC_NCH * (WGC_NJT / 2) * 32];  // WgC^T
__device__ uint4 g_WihPk[WIH_NCH * (WIH_NJT / 2) * 32];  // W_ih^T
__device__ float d_wup[Bn * LPn * 150];
__device__ float d_gu [Bn * LPn * 600];
__device__ unsigned g_flags[NBLK];
__device__ unsigned g_rel2;

// ---------------- smem layout (floats) ----------------
#define WUQ_S  0                      // Wuq fp32 [l*153+h]; P1: Up staging
#define UQH_S  19584                  // Uq fp16 [l*152+d] = 9728 float slots
#define SCR    29312
#define V_S    (SCR + 0)              // 152
#define VB_S   (SCR + 152)            // 152
#define U_S    (SCR + 304)            // 152
#define BSE_S  (SCR + 456)            // 152
#define CC_S   (SCR + 608)            // 152
#define A_S    (SCR + 760)            // 128
#define GU_S   (SCR + 888)            // 600
#define GH_S   (SCR + 1488)           // 464
#define VP_S   (SCR + 1952)           // 80  half2 pairs of v
#define CP2_S  (SCR + 2032)           // 80  half2 pairs of cc
#define RGP_S  (SCR + 2112)           // 320 half2 pairs of rg
#define WVP_S  (SCR + 2432)           // 2 x 192 wv partials
#define BP_S   (SCR + 2816)           // 2 x 640 B partials
#define CPP_S  (SCR + 4096)           // 4 x 512 C partials
#define CCP_S  (SCR + 6144)           // 8 x 152 cc partials
#define AP_S   (SCR + 7360)           // 1024 s partials; P1 staging 9728 from here
#define SMEM_FL (SCR + 7360 + 9728)   // 46400 floats
#define SMEM_BYTES (SMEM_FL * 4)      // 185600 B

// ---------------- helpers ----------------
__device__ __forceinline__ float warp_max_all(float v) {
#pragma unroll
    for (int o = 16; o > 0; o >>= 1) v = fmaxf(v, __shfl_xor_sync(0xffffffffu, v, o));
    return v;
}
__device__ __forceinline__ float warp_sum_all(float v) {
#pragma unroll
    for (int o = 16; o > 0; o >>= 1) v += __shfl_xor_sync(0xffffffffu, v, o);
    return v;
}
__device__ __forceinline__ float fast_sig(float x) {
    return 1.0f / (1.0f + __expf(-x));
}
__device__ __forceinline__ float fast_tanh(float x) {
    float cx = fminf(fmaxf(x, -15.0f), 15.0f);
    float e  = __expf(2.0f * cx);
    return __fdividef(e - 1.0f, e + 1.0f);
}
__device__ __forceinline__ float tanh_fastest(float x) {
    float y;
    asm("tanh.approx.f32 %0, %1;" : "=f"(y) : "f"(x));
    return y;
}
__device__ __forceinline__ unsigned pack2(float x, float y) {
    __half2 h = __floats2half2_rn(x, y);
    return *reinterpret_cast<unsigned*>(&h);
}

// m16n8k16 f16 MMA, f32 accumulate. A rows 1-15 zero (GEMV).
__device__ __forceinline__ void mma16816(float* d, unsigned a0, unsigned a1,
                                         unsigned b0, unsigned b1) {
    asm volatile(
        "mma.sync.aligned.m16n8k16.row.col.f32.f16.f16.f32 "
        "{%0,%1,%2,%3}, {%4,%5,%6,%7}, {%8,%9}, {%0,%1,%2,%3};"
        : "+f"(d[0]), "+f"(d[1]), "+f"(d[2]), "+f"(d[3])
        : "r"(a0), "r"(0u), "r"(a1), "r"(0u), "r"(b0), "r"(b1));
}

// GEMV tile loop over TILE-PAIRS: one LDG.128 per pair feeds 2 MMAs.
// Fully unrolled (KC compile-time) -> ptxas front-batches the loads.
template<int NP, int KC>
__device__ __forceinline__ void gemv_acc4(float d[][4], const uint4* __restrict__ Wpk,
                                          int npr, int kc0, int pr0,
                                          const unsigned* __restrict__ xp, int ln) {
#pragma unroll
    for (int c = 0; c < KC; c++) {
        const int kc = kc0 + c;
        unsigned a0 = 0, a1 = 0;
        if (ln < 4) { a0 = xp[kc * 8 + ln]; a1 = xp[kc * 8 + 4 + ln]; }
        const uint4* wr = Wpk + (kc * npr + pr0) * 32 + ln;
#pragma unroll
        for (int p = 0; p < NP; p++) {
            uint4 bb = __ldg(&wr[p * 32]);
            mma16816(d[2 * p],     a0, a1, bb.x, bb.y);
            mma16816(d[2 * p + 1], a0, a1, bb.z, bb.w);
        }
    }
}
template<int NT>
__device__ __forceinline__ void store_part(const float d[][4], float* dst,
                                           int jt0, int ln) {
    if (ln < 4) {
#pragma unroll
        for (int t = 0; t < NT; t++)
            *(float2*)(dst + (jt0 + t) * 8 + 2 * ln) = make_float2(d[t][0], d[t][1]);
    }
}

// Flag-array grid barrier (prologue only). Monotonic, atomic-free.
__device__ __forceinline__ void gsync(unsigned& gen) {
    __syncthreads();
    const unsigned target = gen + 1u;
    if (blockIdx.x == 0) {
        if (threadIdx.x < 32) {
            const int ln = threadIdx.x;
            if (ln == 0) *((volatile unsigned*)&g_flags[0]) = target;
            bool ok;
            do {
                unsigned f0, f1;
                asm volatile("ld.acquire.gpu.u32 %0, [%1];" : "=r"(f0) : "l"(&g_flags[ln]));
                asm volatile("ld.acquire.gpu.u32 %0, [%1];" : "=r"(f1) : "l"(&g_flags[ln + 32]));
                ok = (f0 >= target) & (f1 >= target);
            } while (!__all_sync(0xffffffffu, ok));
            if (ln == 0)
                asm volatile("st.release.gpu.u32 [%0], %1;" :: "l"(&g_rel2), "r"(target) : "memory");
        }
    } else {
        if (threadIdx.x == 0) {
            asm volatile("st.release.gpu.u32 [%0], %1;"
                         :: "l"(&g_flags[blockIdx.x]), "r"(target) : "memory");
            unsigned r;
            do {
                asm volatile("ld.acquire.gpu.u32 %0, [%1];" : "=r"(r) : "l"(&g_rel2));
            } while (r < target);
        }
    }
    gen = target;
    __syncthreads();
}

// ---------------- the persistent kernel: one block per batch ----------------
__global__ void __launch_bounds__(NTHR, 1) pqm_kernel(
    const float* __restrict__ Up, const float* __restrict__ Uq,
    const float* __restrict__ Wp, const float* __restrict__ Wq,
    const float* __restrict__ Wv, const float* __restrict__ Wg,
    const float* __restrict__ Vmat, const float* __restrict__ v0,
    const float* __restrict__ W_ih, const float* __restrict__ W_hh,
    const float* __restrict__ b_ih, const float* __restrict__ b_hh,
    float* __restrict__ out)
{
    extern __shared__ float sm[];
    __half* UQH = (__half*)(sm + UQH_S);
    unsigned* vpair  = (unsigned*)(sm + VP_S);
    unsigned* ccpair = (unsigned*)(sm + CP2_S);
    unsigned* rgpair = (unsigned*)(sm + RGP_S);
    const int tid = threadIdx.x;
    const int b   = blockIdx.x;
    const int w   = tid >> 5, ln = tid & 31;

    unsigned gen = *((volatile unsigned*)&g_rel2);

    // ======== P0: folds + packed fp16 tile-PAIR weight builds ========
    const int gid = b * NTHR + tid;
    const int gstride = NBLK * NTHR;
    for (int idx = gid; idx < 150 * 152; idx += gstride) {
        int h = idx / 152, d = idx - h * 152;
        d_WpE[idx] = (d < 150) ? Wp[h * 300 + d] + Wp[h * 300 + 150 + d] : 0.f;
        d_WqE[idx] = (d < 150) ? Wq[h * 300 + d] + Wq[h * 300 + 150 + d] : 0.f;
    }
    for (int idx = gid; idx < 600 * 152; idx += gstride) {
        int j = idx / 152, k = idx - j * 152;
        d_WgU[idx] = (k < 150) ? Wg[j * 600 + k] + Wg[j * 600 + 150 + k] : 0.f;
    }
    // Wv^T: W[k][j] = Wv[j*150+k], k<150, j<150
    for (int idx = gid; idx < WV_NCH * (WV_NJT / 2) * 32; idx += gstride) {
        int lane = idx & 31, rest = idx >> 5;
        int pr = rest % (WV_NJT / 2), kc = rest / (WV_NJT / 2);
        int m = lane & 3, jr = lane >> 2;
        int k0 = kc * 16 + 2 * m;
        unsigned pk[2];
#pragma unroll
        for (int t = 0; t < 2; t++) {
            int j = 8 * (2 * pr + t) + jr;
            float v00 = 0.f, v01 = 0.f, v10 = 0.f, v11 = 0.f;
            if (j < 150) {
                if (k0     < 150) v00 = Wv[j * 150 + k0];
                if (k0 + 1 < 150) v01 = Wv[j * 150 + k0 + 1];
                if (k0 + 8 < 150) v10 = Wv[j * 150 + k0 + 8];
                if (k0 + 9 < 150) v11 = Wv[j * 150 + k0 + 9];
            }
            pk[t] = 0;  // silence unused warning path
            if (t == 0) { g_WvPk[idx].x = pack2(v00, v01); g_WvPk[idx].y = pack2(v10, v11); }
            else        { g_WvPk[idx].z = pack2(v00, v01); g_WvPk[idx].w = pack2(v10, v11); }
        }
        (void)pk;
    }
    // W_hh^T: W[k][j] = W_hh[j*150+k], k<150, j<450
    for (int idx = gid; idx < WHH_NCH * (WHH_NJT / 2) * 32; idx += gstride) {
        int lane = idx & 31, rest = idx >> 5;
        int pr = rest % (WHH_NJT / 2), kc = rest / (WHH_NJT / 2);
        int m = lane & 3, jr = lane >> 2;
        int k0 = kc * 16 + 2 * m;
#pragma unroll
        for (int t = 0; t < 2; t++) {
            int j = 8 * (2 * pr + t) + jr;
            float v00 = 0.f, v01 = 0.f, v10 = 0.f, v11 = 0.f;
            if (j < 450) {
                if (k0     < 150) v00 = W_hh[j * 150 + k0];
                if (k0 + 1 < 150) v01 = W_hh[j * 150 + k0 + 1];
                if (k0 + 8 < 150) v10 = W_hh[j * 150 + k0 + 8];
                if (k0 + 9 < 150) v11 = W_hh[j * 150 + k0 + 9];
            }
            if (t == 0) { g_WhhPk[idx].x = pack2(v00, v01); g_WhhPk[idx].y = pack2(v10, v11); }
            else        { g_WhhPk[idx].z = pack2(v00, v01); g_WhhPk[idx].w = pack2(v10, v11); }
        }
    }
    // WgC^T: W[k][j] = Wg[j*600+300+k] + Wg[j*600+450+k], k<150, j<600
    for (int idx = gid; idx < WGC_NCH * (WGC_NJT / 2) * 32; idx += gstride) {
        int lane = idx & 31, rest = idx >> 5;
        int pr = rest % (WGC_NJT / 2), kc = rest / (WGC_NJT / 2);
        int m = lane & 3, jr = lane >> 2;
        int k0 = kc * 16 + 2 * m;
#pragma unroll
        for (int t = 0; t < 2; t++) {
            int j = 8 * (2 * pr + t) + jr;
            float v00 = 0.f, v01 = 0.f, v10 = 0.f, v11 = 0.f;
            if (j < 600) {
                if (k0     < 150) v00 = Wg[j * 600 + 300 + k0]     + Wg[j * 600 + 450 + k0];
                if (k0 + 1 < 150) v01 = Wg[j * 600 + 300 + k0 + 1] + Wg[j * 600 + 450 + k0 + 1];
                if (k0 + 8 < 150) v10 = Wg[j * 600 + 300 + k0 + 8] + Wg[j * 600 + 450 + k0 + 8];
                if (k0 + 9 < 150) v11 = Wg[j * 600 + 300 + k0 + 9] + Wg[j * 600 + 450 + k0 + 9];
            }
            if (t == 0) { g_WgCPk[idx].x = pack2(v00, v01); g_WgCPk[idx].y = pack2(v10, v11); }
            else        { g_WgCPk[idx].z = pack2(v00, v01); g_WgCPk[idx].w = pack2(v10, v11); }
        }
    }
    // W_ih^T: W[k][j] = W_ih[j*600+k], k<600, j<450
    for (int idx = gid; idx < WIH_NCH * (WIH_NJT / 2) * 32; idx += gstride) {
        int lane = idx & 31, rest = idx >> 5;
        int pr = rest % (WIH_NJT / 2), kc = rest / (WIH_NJT / 2);
        int m = lane & 3, jr = lane >> 2;
        int k0 = kc * 16 + 2 * m;
#pragma unroll
        for (int t = 0; t < 2; t++) {
            int j = 8 * (2 * pr + t) + jr;
            float v00 = 0.f, v01 = 0.f, v10 = 0.f, v11 = 0.f;
            if (j < 450) {
                if (k0     < 600) v00 = W_ih[j * 600 + k0];
                if (k0 + 1 < 600) v01 = W_ih[j * 600 + k0 + 1];
                if (k0 + 8 < 600) v10 = W_ih[j * 600 + k0 + 8];
                if (k0 + 9 < 600) v11 = W_ih[j * 600 + k0 + 9];
            }
            if (t == 0) { g_WihPk[idx].x = pack2(v00, v01); g_WihPk[idx].y = pack2(v10, v11); }
            else        { g_WihPk[idx].z = pack2(v00, v01); g_WihPk[idx].w = pack2(v10, v11); }
        }
    }
    gsync(gen);   // the ONLY grid barrier

    // ======== P1 (block-local): per-batch precompute ========
    {
        float* A = sm + WUQ_S;     // Up staging [i*152+k]
        for (int t = tid; t < 128 * 150; t += NTHR) {
            int ii = t / 150, k = t - ii * 150;
            A[ii * 152 + k] = Up[(ii * Bn + b) * 150 + k];
        }
        __syncthreads();
        for (int task = tid; task < 16 * 600; task += NTHR) {
            int j = task % 600, it = task / 600;
            float acc[8] = {0.f, 0.f, 0.f, 0.f, 0.f, 0.f, 0.f, 0.f};
            const float4* wr = (const float4*)(d_WgU + j * 152);
            for (int q = 0; q < 38; q++) {
                float4 w4 = wr[q];
#pragma unroll
                for (int ii = 0; ii < 8; ii++) {
                    const float* xr = A + (it * 8 + ii) * 152 + q * 4;
                    acc[ii] += w4.x * xr[0] + w4.y * xr[1] + w4.z * xr[2] + w4.w * xr[3];
                }
            }
#pragma unroll
            for (int ii = 0; ii < 8; ii++)
                d_gu[(b * LPn + it * 8 + ii) * 600 + j] = acc[ii];
        }
        for (int task = tid; task < 16 * 150; task += NTHR) {
            int h = task % 150, it = task / 150;
            float acc[8] = {0.f, 0.f, 0.f, 0.f, 0.f, 0.f, 0.f, 0.f};
            const float4* wr = (const float4*)(d_WpE + h * 152);
            for (int q = 0; q < 38; q++) {
                float4 w4 = wr[q];
#pragma unroll
                for (int ii = 0; ii < 8; ii++) {
                    const float* xr = A + (it * 8 + ii) * 152 + q * 4;
                    acc[ii] += w4.x * xr[0] + w4.y * xr[1] + w4.z * xr[2] + w4.w * xr[3];
                }
            }
#pragma unroll
            for (int ii = 0; ii < 8; ii++)
                d_wup[(b * LPn + it * 8 + ii) * 150 + h] = acc[ii];
        }
        __syncthreads();
        float* S2 = sm + AP_S;
        for (int ph = 0; ph < 2; ph++) {
            for (int t = tid; t < 64 * 150; t += NTHR) {
                int ll = t / 150, d = t - ll * 150;
                float vv = Uq[((ph * 64 + ll) * Bn + b) * 150 + d];
                S2[ll * 152 + d] = vv;
                UQH[(ph * 64 + ll) * 152 + d] = __float2half_rn(vv);
            }
            __syncthreads();
            for (int task = tid; task < 8 * 150; task += NTHR) {
                int h = task % 150, lt = task / 150;
                float acc[8] = {0.f, 0.f, 0.f, 0.f, 0.f, 0.f, 0.f, 0.f};
                const float4* wr = (const float4*)(d_WqE + h * 152);
                for (int q = 0; q < 38; q++) {
                    float4 w4 = wr[q];
#pragma unroll
                    for (int ii = 0; ii < 8; ii++) {
                        const float* xr = S2 + (lt * 8 + ii) * 152 + q * 4;
                        acc[ii] += w4.x * xr[0] + w4.y * xr[1] + w4.z * xr[2] + w4.w * xr[3];
                    }
                }
#pragma unroll
                for (int ii = 0; ii < 8; ii++)
                    sm[WUQ_S + (ph * 64 + lt * 8 + ii) * 153 + h] = acc[ii];
            }
            __syncthreads();
        }
        if (tid < 150) {
            sm[V_S + tid]  = v0[b * 150 + tid];
            sm[VB_S + tid] = Vmat[b * 150 + tid];
        }
        __syncthreads();
        if (tid < 80) {
            float x0 = (2 * tid     < 150) ? sm[V_S + 2 * tid]     : 0.f;
            float x1 = (2 * tid + 1 < 150) ? sm[V_S + 2 * tid + 1] : 0.f;
            vpair[tid] = pack2(x0, x1);
        }
        if (tid >= 128 && tid < 133) ccpair[75 + tid - 128] = 0u;
        if (tid >= 160 && tid < 180) rgpair[300 + tid - 160] = 0u;
    }
    __syncthreads();

    // ======== main scan: 128 steps, block-local ========
    for (int i = 0; i < LPn; i++) {
        // ---- Stage A: wv mma (w0-7) | gh mma (w8-23) | staging (w24-31) ----
        if (w < 8) {
            int kg = w >> 2, jg = w & 3;      // 2 kg x 4 jg, 3 pairs (6 tiles) each
            float d[6][4];
#pragma unroll
            for (int t = 0; t < 6; t++) { d[t][0]=d[t][1]=d[t][2]=d[t][3]=0.f; }
            gemv_acc4<3, 5>(d, g_WvPk, WV_NJT / 2, kg * 5, jg * 3, vpair, ln);
            store_part<6>(d, sm + WVP_S + kg * 192, jg * 6, ln);
        } else if (w < 24) {
            int wl = w - 8;                   // 16 warps, 2 pairs (4 tiles), full k
            int jt0 = wl * 4;
            float d[4][4];
#pragma unroll
            for (int t = 0; t < 4; t++) { d[t][0]=d[t][1]=d[t][2]=d[t][3]=0.f; }
            gemv_acc4<2, 10>(d, g_WhhPk, WHH_NJT / 2, 0, wl * 2, vpair, ln);
            if (ln < 4) {
#pragma unroll
                for (int t = 0; t < 4; t++) {
                    int j = (jt0 + t) * 8 + 2 * ln;
                    if (j < 450) {
                        sm[GH_S + j]     = d[t][0] + b_hh[j];
                        sm[GH_S + j + 1] = d[t][1] + b_hh[j + 1];
                    }
                }
            }
        } else {
            for (int t = tid - 768; t < 900; t += 256) {
                if (t < 150)      sm[U_S + t]         = Up[(i * Bn + b) * 150 + t];
                else if (t < 300) sm[BSE_S + t - 150] = d_wup[(b * LPn + i) * 150 + t - 150];
                else              sm[GU_S + t - 300]  = d_gu[(b * LPn + i) * 600 + t - 300];
            }
        }
        __syncthreads();
        // ---- bse combine ----
        if (tid < 150) sm[BSE_S + tid] += sm[WVP_S + tid] + sm[WVP_S + 192 + tid];
        __syncthreads();
        // ---- S3: s[l] partials (128 l x 8 k-groups) ----
        {
            int l = tid & 127, g = tid >> 7;
            int k0 = (g * 150) >> 3, k1 = ((g + 1) * 150) >> 3;
            const float* wq = sm + WUQ_S + l * 153;
            float acc = 0.f;
#pragma unroll 10
            for (int k = k0; k < k1; k++)
                acc += tanh_fastest(sm[BSE_S + k] + wq[k]) * sm[VB_S + k];
            sm[AP_S + g * 128 + l] = acc;
        }
        __syncthreads();
        // ---- softmax (warp 0) ----
        if (w == 0) {
            float a0 = 0.f, a1 = 0.f, a2 = 0.f, a3 = 0.f;
#pragma unroll
            for (int g = 0; g < 8; g++) {
                const float* apg = sm + AP_S + g * 128;
                a0 += apg[ln]; a1 += apg[32 + ln]; a2 += apg[64 + ln]; a3 += apg[96 + ln];
            }
            float m = fmaxf(fmaxf(a0, a1), fmaxf(a2, a3));
            m = warp_max_all(m);
            float e0 = __expf(a0 - m), e1 = __expf(a1 - m);
            float e2 = __expf(a2 - m), e3 = __expf(a3 - m);
            float ssum = warp_sum_all(e0 + e1 + e2 + e3);
            float inv = __fdividef(1.0f, ssum);
            sm[A_S + ln] = e0 * inv; sm[A_S + 32 + ln] = e1 * inv;
            sm[A_S + 64 + ln] = e2 * inv; sm[A_S + 96 + ln] = e3 * inv;
        }
        __syncthreads();
        // ---- cc partials (8 l-groups x 150 d) ----
        for (int t = tid; t < 1200; t += NTHR) {
            int lq = t / 150, d = t - lq * 150;
            const __half* uq = UQH + lq * 16 * 152 + d;
            const float* av = sm + A_S + lq * 16;
            float acc = 0.f;
#pragma unroll
            for (int q = 0; q < 16; q++) acc += av[q] * __half2float(uq[q * 152]);
            sm[CCP_S + lq * 152 + d] = acc;
        }
        __syncthreads();
        // ---- cc combine (75 thr, 2 cols each) + pairs ----
        if (tid < 75) {
            float c0 = 0.f, c1 = 0.f;
            int d0 = 2 * tid, d1 = d0 + 1;
#pragma unroll
            for (int g = 0; g < 8; g++) {
                c0 += sm[CCP_S + g * 152 + d0];
                c1 += sm[CCP_S + g * 152 + d1];
            }
            sm[CC_S + d0] = c0; sm[CC_S + d1] = c1;
            ccpair[tid] = pack2(c0, c1);
        }
        __syncthreads();
        // ---- B mma (all 32): bp = cc @ WgC^T partials (2 kg x 16 jg) ----
        {
            int kg = w >> 4, jg = w & 15;
            if (jg < 8) {
                float d[6][4];
#pragma unroll
                for (int t = 0; t < 6; t++) { d[t][0]=d[t][1]=d[t][2]=d[t][3]=0.f; }
                gemv_acc4<3, 5>(d, g_WgCPk, WGC_NJT / 2, kg * 5, jg * 3, ccpair, ln);
                store_part<6>(d, sm + BP_S + kg * 640, jg * 6, ln);
            } else {
                float d[4][4];
#pragma unroll
                for (int t = 0; t < 4; t++) { d[t][0]=d[t][1]=d[t][2]=d[t][3]=0.f; }
                gemv_acc4<2, 5>(d, g_WgCPk, WGC_NJT / 2, kg * 5, 24 + (jg - 8) * 2, ccpair, ln);
                store_part<4>(d, sm + BP_S + kg * 640, 48 + (jg - 8) * 4, ln);
            }
        }
        __syncthreads();
        // ---- B combine (300 thr, 2 j each): rg pairs ----
        if (tid < 300) {
            float r2[2];
#pragma unroll
            for (int s = 0; s < 2; s++) {
                int j = 2 * tid + s;
                float g = sm[GU_S + j] + sm[BP_S + j] + sm[BP_S + 640 + j];
                float sg = fast_sig(g);
                int km = (j < 150) ? j : (j < 300) ? j - 150 : (j < 450) ? j - 300 : j - 450;
                float rb = (j < 300) ? sm[U_S + km] : sm[CC_S + km];
                r2[s] = sg * rb;
            }
            rgpair[tid] = pack2(r2[0], r2[1]);
        }
        __syncthreads();
        // ---- C mma (all 32): cp = rg @ W_ih^T partials (4 kg x 8 jg, 4 pairs) ----
        {
            int kg = w >> 3, jg = w & 7;
            float d[8][4];
#pragma unroll
            for (int t = 0; t < 8; t++) { d[t][0]=d[t][1]=d[t][2]=d[t][3]=0.f; }
            gemv_acc4<4, 10>(d, g_WihPk, WIH_NJT / 2, kg * 10, jg * 4, rgpair, ln);
            store_part<8>(d, sm + CPP_S + kg * 512, jg * 8, ln);
        }
        __syncthreads();
        // ---- GRU combine (75 thr, 2 h each) + v pairs ----
        if (tid < 75) {
            float hn2[2];
#pragma unroll
            for (int s = 0; s < 2; s++) {
                int h = 2 * tid + s;
                float ir = b_ih[h], iz = b_ih[150 + h], in_ = b_ih[300 + h];
#pragma unroll
                for (int g = 0; g < 4; g++) {
                    const float* cp = sm + CPP_S + g * 512;
                    ir += cp[h]; iz += cp[150 + h]; in_ += cp[300 + h];
                }
                float r_ = fast_sig(ir + sm[GH_S + h]);
                float z_ = fast_sig(iz + sm[GH_S + 150 + h]);
                float n_ = fast_tanh(in_ + r_ * sm[GH_S + 300 + h]);
                float hnew = (1.0f - z_) * n_ + z_ * sm[V_S + h];
                out[(i * Bn + b) * 150 + h] = hnew;
                sm[V_S + h] = hnew;
                hn2[s] = hnew;
            }
            vpair[tid] = pack2(hn2[0], hn2[1]);
        }
        __syncthreads();
    }
}

// ---------------- launch ----------------
extern "C" void kernel_launch(void* const* d_in, const int* in_sizes, int n_in,
                              void* d_out, int out_size)
{
    const float* Up   = (const float*)d_in[0];
    const float* Uq   = (const float*)d_in[1];
    const float* Wp   = (const float*)d_in[2];
    const float* Wq   = (const float*)d_in[3];
    const float* Wv   = (const float*)d_in[4];
    const float* Wg   = (const float*)d_in[5];
    const float* Vm   = (const float*)d_in[6];
    const float* v0   = (const float*)d_in[7];
    const float* W_ih = (const float*)d_in[8];
    const float* W_hh = (const float*)d_in[9];
    const float* b_ih = (const float*)d_in[10];
    const float* b_hh = (const float*)d_in[11];
    float* out = (float*)d_out;

    cudaFuncSetAttribute(pqm_kernel, cudaFuncAttributeMaxDynamicSharedMemorySize, SMEM_BYTES);
    pqm_kernel<<<NBLK, NTHR, SMEM_BYTES>>>(Up, Uq, Wp, Wq, Wv, Wg, Vm, v0,
                                           W_ih, W_hh, b_ih, b_hh, out);
}